// round 2
// baseline (speedup 1.0000x reference)
#include <cuda_runtime.h>

#define NC 25000
#define CF 128

// Scratch (allocation-free rule: __device__ globals)
__device__ float g_pooled[NC * CF];
__device__ float g_S[NC * CF];
__device__ float g_h1[NC * CF];

// ---------------------------------------------------------------------------
// zero fill
// ---------------------------------------------------------------------------
__global__ void zero_kernel(float4* __restrict__ p, int n4) {
    int i = blockIdx.x * blockDim.x + threadIdx.x;
    if (i < n4) p[i] = make_float4(0.f, 0.f, 0.f, 0.f);
}

// ---------------------------------------------------------------------------
// scatter: out[dst[e]] += w[e] * src[sidx[e]]   (one warp per edge, 32 x float4)
// ---------------------------------------------------------------------------
__global__ void scatter_kernel(const float* __restrict__ src,
                               const int* __restrict__ sidx,
                               const int* __restrict__ didx,
                               const float* __restrict__ w,
                               float* __restrict__ out,
                               int E) {
    int gw   = (int)((blockIdx.x * blockDim.x + threadIdx.x) >> 5);
    int lane = threadIdx.x & 31;
    if (gw >= E) return;
    int   s  = __ldg(&sidx[gw]);
    int   d  = __ldg(&didx[gw]);
    float we = __ldg(&w[gw]);
    float4 v = *(const float4*)(src + (size_t)s * CF + lane * 4);
    v.x *= we; v.y *= we; v.z *= we; v.w *= we;
    float* dp = out + (size_t)d * CF + lane * 4;
    asm volatile("red.global.add.v4.f32 [%0], {%1, %2, %3, %4};"
                 :: "l"(dp), "f"(v.x), "f"(v.y), "f"(v.z), "f"(v.w)
                 : "memory");
}

// ---------------------------------------------------------------------------
// fused GEMM: out = A @ Wr + B @ Wn + bias     (A,B: [n,128]; W: [128,128])
// Block: 128 rows x 128 cols, 256 threads, per-thread 8 rows x 8 cols (as 4
// f32x2 pairs at cols cg*2 + 32*j -> conflict-free smem W reads).
// K streamed in 8 chunks of 32 (4 from A/Wr, 4 from B/Wn).
// Inner product uses Blackwell packed fma.rn.f32x2 (2 FMA/lane-op).
// ---------------------------------------------------------------------------
__global__ __launch_bounds__(256) void gemm_kernel(
        const float* __restrict__ A,
        const float* __restrict__ B,
        const float* __restrict__ Wr,
        const float* __restrict__ Wn,
        const float* __restrict__ bias,
        float* __restrict__ out,
        int n) {
    __shared__ float xs[32][130];   // transposed X chunk, padded (8B-aligned, bank-safe)
    __shared__ float ws[32][128];   // W chunk

    int tid = threadIdx.x;
    int rg  = tid >> 4;     // 0..15  row group (8 rows)
    int cg  = tid & 15;     // 0..15  col group (pairs at cg*2 + 32*j)
    int rowBase = blockIdx.x * 128;
    int r0 = rg * 8;

    unsigned long long acc[8][4];
    #pragma unroll
    for (int j = 0; j < 4; j++) {
        int c = cg * 2 + 32 * j;
        float b0 = bias[c], b1 = bias[c + 1];
        unsigned long long p;
        asm("mov.b64 %0, {%1, %2};" : "=l"(p) : "f"(b0), "f"(b1));
        #pragma unroll
        for (int i = 0; i < 8; i++) acc[i][j] = p;
    }

    for (int kc = 0; kc < 8; kc++) {
        const float* X = (kc < 4) ? A : B;
        const float* W = (kc < 4) ? Wr : Wn;
        int kbase = (kc & 3) * 32;

        // stage X chunk transposed: xs[k][row] = X[rowBase+row][kbase+k]
        #pragma unroll
        for (int it = 0; it < 4; it++) {
            int idx = it * 256 + tid;
            int row = idx >> 3;       // 0..127
            int f4  = idx & 7;        // 0..7
            int grow = rowBase + row;
            float4 v = make_float4(0.f, 0.f, 0.f, 0.f);
            if (grow < n) v = *(const float4*)(X + (size_t)grow * CF + kbase + f4 * 4);
            xs[f4 * 4 + 0][row] = v.x;
            xs[f4 * 4 + 1][row] = v.y;
            xs[f4 * 4 + 2][row] = v.z;
            xs[f4 * 4 + 3][row] = v.w;
        }
        // stage W chunk: ws[k][c] = W[kbase+k][c]
        #pragma unroll
        for (int it = 0; it < 4; it++) {
            int idx = it * 256 + tid;
            int k   = idx >> 5;       // 0..31
            int f4c = idx & 31;       // 0..31
            *(float4*)&ws[k][f4c * 4] =
                *(const float4*)(W + (size_t)(kbase + k) * CF + f4c * 4);
        }
        __syncthreads();

        #pragma unroll
        for (int k = 0; k < 32; k++) {
            unsigned long long apair[8];
            #pragma unroll
            for (int h = 0; h < 4; h++) {
                float2 a2 = *(const float2*)&xs[k][r0 + h * 2];
                unsigned long long p0, p1;
                asm("mov.b64 %0, {%1, %2};" : "=l"(p0) : "f"(a2.x), "f"(a2.x));
                asm("mov.b64 %0, {%1, %2};" : "=l"(p1) : "f"(a2.y), "f"(a2.y));
                apair[h * 2]     = p0;
                apair[h * 2 + 1] = p1;
            }
            #pragma unroll
            for (int j = 0; j < 4; j++) {
                unsigned long long wv =
                    *(const unsigned long long*)&ws[k][cg * 2 + 32 * j];
                #pragma unroll
                for (int i = 0; i < 8; i++) {
                    asm("fma.rn.f32x2 %0, %1, %2, %0;"
                        : "+l"(acc[i][j]) : "l"(apair[i]), "l"(wv));
                }
            }
        }
        __syncthreads();
    }

    #pragma unroll
    for (int i = 0; i < 8; i++) {
        int grow = rowBase + r0 + i;
        if (grow < n) {
            #pragma unroll
            for (int j = 0; j < 4; j++) {
                int c = cg * 2 + 32 * j;
                float lo, hi;
                asm("mov.b64 {%0, %1}, %2;" : "=f"(lo), "=f"(hi) : "l"(acc[i][j]));
                *(float2*)(out + (size_t)grow * CF + c) = make_float2(lo, hi);
            }
        }
    }
}

// ---------------------------------------------------------------------------
// launch
// ---------------------------------------------------------------------------
extern "C" void kernel_launch(void* const* d_in, const int* in_sizes, int n_in,
                              void* d_out, int out_size) {
    const float* x       = (const float*)d_in[0];
    const int*   pool_ei = (const int*)d_in[1];     // [2, E_pool] int32 (JAX x64 off)
    const float* pool_w  = (const float*)d_in[2];
    const int*   ei      = (const int*)d_in[3];     // [2, E] int32
    const float* ew      = (const float*)d_in[4];
    const float* W1r     = (const float*)d_in[5];
    const float* W1n     = (const float*)d_in[6];
    const float* b1      = (const float*)d_in[7];
    const float* W2r     = (const float*)d_in[8];
    const float* W2n     = (const float*)d_in[9];
    const float* b2      = (const float*)d_in[10];

    int Ep = in_sizes[2];   // pooling edge count (pool_edge_attr length)
    int E  = in_sizes[4];   // coarse edge count

    float *pooled, *S, *h1;
    cudaGetSymbolAddress((void**)&pooled, g_pooled);
    cudaGetSymbolAddress((void**)&S,      g_S);
    cudaGetSymbolAddress((void**)&h1,     g_h1);

    const int n4 = NC * CF / 4;
    const int zb = (n4 + 255) / 256;

    zero_kernel<<<zb, 256>>>((float4*)pooled, n4);
    zero_kernel<<<zb, 256>>>((float4*)S, n4);

    // pooled[dst] += w * x[src]   (fine -> coarse)
    scatter_kernel<<<(Ep + 7) / 8, 256>>>(x, pool_ei, pool_ei + Ep, pool_w, pooled, Ep);

    // S = scatter(w * pooled[src] -> dst)
    scatter_kernel<<<(E + 7) / 8, 256>>>(pooled, ei, ei + E, ew, S, E);

    // h1 = pooled @ W1r + S @ W1n + b1
    gemm_kernel<<<(NC + 127) / 128, 256>>>(pooled, S, W1r, W1n, b1, h1, NC);

    zero_kernel<<<zb, 256>>>((float4*)S, n4);

    // S = scatter(w * h1[src] -> dst)
    scatter_kernel<<<(E + 7) / 8, 256>>>(h1, ei, ei + E, ew, S, E);

    // out = h1 @ W2r + S @ W2n + b2
    gemm_kernel<<<(NC + 127) / 128, 256>>>(h1, S, W2r, W2n, b2, (float*)d_out, NC);
}

// round 3
// speedup vs baseline: 1.0460x; 1.0460x over previous
#include <cuda_runtime.h>

#define NC 25000
#define NF 100000
#define CF 128
#define EMAX 400000
#define EPMAX 200000

// Scratch (__device__ globals; no allocations allowed)
__device__ float g_pooled[NC * CF];
__device__ float g_S[NC * CF];
__device__ float g_h1[NC * CF];

__device__ int   g_deg_c[NC];
__device__ int   g_off_c[NC];
__device__ int   g_cur_c[NC];
__device__ int   g_csrc_c[EMAX];
__device__ float g_cw_c[EMAX];

__device__ int   g_deg_p[NC];
__device__ int   g_off_p[NC];
__device__ int   g_cur_p[NC];
__device__ int   g_csrc_p[EPMAX];
__device__ float g_cw_p[EPMAX];

// ---------------------------------------------------------------------------
// zero both degree arrays
// ---------------------------------------------------------------------------
__global__ void zero_deg_kernel(int* __restrict__ a, int* __restrict__ b, int n) {
    int i = blockIdx.x * blockDim.x + threadIdx.x;
    if (i < n) { a[i] = 0; b[i] = 0; }
}

// ---------------------------------------------------------------------------
// histogram of both dst arrays in one launch
// ---------------------------------------------------------------------------
__global__ void hist2_kernel(const int* __restrict__ dstC, int* __restrict__ degC, int EC,
                             const int* __restrict__ dstP, int* __restrict__ degP, int EP_) {
    int i = blockIdx.x * blockDim.x + threadIdx.x;
    if (i < EC) {
        atomicAdd(&degC[__ldg(&dstC[i])], 1);
    } else {
        int k = i - EC;
        if (k < EP_) atomicAdd(&degP[__ldg(&dstP[k])], 1);
    }
}

// ---------------------------------------------------------------------------
// exclusive scan (both edge sets: block 0 = coarse, block 1 = pool)
// ---------------------------------------------------------------------------
__global__ void scan2_kernel(const int* __restrict__ degA, int* __restrict__ offA, int* __restrict__ curA,
                             const int* __restrict__ degB, int* __restrict__ offB, int* __restrict__ curB,
                             int n) {
    const int* deg = blockIdx.x ? degB : degA;
    int* off = blockIdx.x ? offB : offA;
    int* cur = blockIdx.x ? curB : curA;

    __shared__ int ssum[1024];
    int tid = threadIdx.x;
    const int CH = (n + 1023) / 1024;
    int base = tid * CH;
    int s = 0;
    for (int i = 0; i < CH; i++) {
        int idx = base + i;
        if (idx < n) s += deg[idx];
    }
    ssum[tid] = s;
    __syncthreads();
    for (int d = 1; d < 1024; d <<= 1) {
        int v = (tid >= d) ? ssum[tid - d] : 0;
        __syncthreads();
        ssum[tid] += v;
        __syncthreads();
    }
    int run = (tid == 0) ? 0 : ssum[tid - 1];
    for (int i = 0; i < CH; i++) {
        int idx = base + i;
        if (idx < n) {
            off[idx] = run;
            cur[idx] = run;
            run += deg[idx];
        }
    }
}

// ---------------------------------------------------------------------------
// fill CSR bins (src, w packed per-bin) for both edge sets
// ---------------------------------------------------------------------------
__global__ void fill2_kernel(const int* __restrict__ srcC, const int* __restrict__ dstC,
                             const float* __restrict__ wC, int* __restrict__ curC,
                             int* __restrict__ csC, float* __restrict__ cwC, int EC,
                             const int* __restrict__ srcP, const int* __restrict__ dstP,
                             const float* __restrict__ wP, int* __restrict__ curP,
                             int* __restrict__ csP, float* __restrict__ cwP, int EP_) {
    int i = blockIdx.x * blockDim.x + threadIdx.x;
    if (i < EC) {
        int d = __ldg(&dstC[i]);
        int idx = atomicAdd(&curC[d], 1);
        csC[idx] = __ldg(&srcC[i]);
        cwC[idx] = __ldg(&wC[i]);
    } else {
        int k = i - EC;
        if (k < EP_) {
            int d = __ldg(&dstP[k]);
            int idx = atomicAdd(&curP[d], 1);
            csP[idx] = __ldg(&srcP[k]);
            cwP[idx] = __ldg(&wP[k]);
        }
    }
}

// ---------------------------------------------------------------------------
// gather-side aggregation: out[node] = sum_j w_j * X[src_j]   (warp per node)
// ---------------------------------------------------------------------------
__global__ void gather_kernel(const float* __restrict__ X,
                              const int* __restrict__ off,
                              const int* __restrict__ deg,
                              const int* __restrict__ csrc,
                              const float* __restrict__ cw,
                              float* __restrict__ out, int n) {
    int node = (int)((blockIdx.x * blockDim.x + threadIdx.x) >> 5);
    int lane = threadIdx.x & 31;
    if (node >= n) return;
    int o = __ldg(&off[node]);
    int d = __ldg(&deg[node]);
    float4 acc = make_float4(0.f, 0.f, 0.f, 0.f);
    int j = 0;
    for (; j + 4 <= d; j += 4) {
        int   s0 = __ldg(&csrc[o + j]);
        int   s1 = __ldg(&csrc[o + j + 1]);
        int   s2 = __ldg(&csrc[o + j + 2]);
        int   s3 = __ldg(&csrc[o + j + 3]);
        float w0 = __ldg(&cw[o + j]);
        float w1 = __ldg(&cw[o + j + 1]);
        float w2 = __ldg(&cw[o + j + 2]);
        float w3 = __ldg(&cw[o + j + 3]);
        float4 v0 = *(const float4*)(X + (size_t)s0 * CF + lane * 4);
        float4 v1 = *(const float4*)(X + (size_t)s1 * CF + lane * 4);
        float4 v2 = *(const float4*)(X + (size_t)s2 * CF + lane * 4);
        float4 v3 = *(const float4*)(X + (size_t)s3 * CF + lane * 4);
        acc.x = fmaf(w0, v0.x, fmaf(w1, v1.x, fmaf(w2, v2.x, fmaf(w3, v3.x, acc.x))));
        acc.y = fmaf(w0, v0.y, fmaf(w1, v1.y, fmaf(w2, v2.y, fmaf(w3, v3.y, acc.y))));
        acc.z = fmaf(w0, v0.z, fmaf(w1, v1.z, fmaf(w2, v2.z, fmaf(w3, v3.z, acc.z))));
        acc.w = fmaf(w0, v0.w, fmaf(w1, v1.w, fmaf(w2, v2.w, fmaf(w3, v3.w, acc.w))));
    }
    for (; j < d; j++) {
        int   s = __ldg(&csrc[o + j]);
        float w = __ldg(&cw[o + j]);
        float4 v = *(const float4*)(X + (size_t)s * CF + lane * 4);
        acc.x = fmaf(w, v.x, acc.x);
        acc.y = fmaf(w, v.y, acc.y);
        acc.z = fmaf(w, v.z, acc.z);
        acc.w = fmaf(w, v.w, acc.w);
    }
    *(float4*)(out + (size_t)node * CF + lane * 4) = acc;
}

// ---------------------------------------------------------------------------
// fused GEMM: out = A @ Wr + B @ Wn + bias  (A,B: [n,128]; W: [128,128])
// 96-row x 128-col tiles, 256 threads, per-thread 6 rows x 8 cols.
// Row-paired f32x2 accumulators: a-operand = direct LDS.64 of 2 consecutive
// rows from transposed smem; w-operand read from smem pre-duplicated pairs.
// 261 blocks -> single resident wave (2 blocks/SM fits smem+regs).
// ---------------------------------------------------------------------------
#define TR 96   // rows per block
__global__ __launch_bounds__(256) void gemm_kernel(
        const float* __restrict__ A,
        const float* __restrict__ B,
        const float* __restrict__ Wr,
        const float* __restrict__ Wn,
        const float* __restrict__ bias,
        float* __restrict__ out,
        int n) {
    __shared__ float xs[32][TR + 2];    // transposed X chunk (row stride 98: 8B-aligned)
    __shared__ float ws2[32][256];      // W chunk, each value duplicated (pair layout)

    int tid = threadIdx.x;
    int rg  = tid >> 4;     // 0..15 row group (6 rows)
    int cg  = tid & 15;     // cols cg + 16*j, j=0..7
    int rowBase = blockIdx.x * TR;
    int r0 = rg * 6;

    unsigned long long acc[3][8];
    #pragma unroll
    for (int j = 0; j < 8; j++) {
        float b = __ldg(&bias[cg + 16 * j]);
        unsigned long long p;
        asm("mov.b64 %0, {%1, %2};" : "=l"(p) : "f"(b), "f"(b));
        #pragma unroll
        for (int ri = 0; ri < 3; ri++) acc[ri][j] = p;
    }

    for (int kc = 0; kc < 8; kc++) {
        const float* X = (kc < 4) ? A : B;
        const float* W = (kc < 4) ? Wr : Wn;
        int kbase = (kc & 3) * 32;

        // stage X chunk transposed: xs[k][row] = X[rowBase+row][kbase+k]
        #pragma unroll
        for (int it = 0; it < 3; it++) {
            int idx = it * 256 + tid;       // 0..767 = 96 rows * 8 float4
            int row = idx >> 3;
            int f4  = idx & 7;
            int grow = rowBase + row;
            float4 v = make_float4(0.f, 0.f, 0.f, 0.f);
            if (grow < n) v = *(const float4*)(X + (size_t)grow * CF + kbase + f4 * 4);
            xs[f4 * 4 + 0][row] = v.x;
            xs[f4 * 4 + 1][row] = v.y;
            xs[f4 * 4 + 2][row] = v.z;
            xs[f4 * 4 + 3][row] = v.w;
        }
        // stage W chunk duplicated: ws2[k][2c],[2c+1] = W[kbase+k][c]
        #pragma unroll
        for (int it = 0; it < 4; it++) {
            int idx = it * 256 + tid;       // 0..1023 float4s of W
            int k   = idx >> 5;
            int c4  = idx & 31;
            float4 v = *(const float4*)(W + (size_t)(kbase + k) * CF + c4 * 4);
            float4* w4 = (float4*)&ws2[k][c4 * 8];
            w4[0] = make_float4(v.x, v.x, v.y, v.y);
            w4[1] = make_float4(v.z, v.z, v.w, v.w);
        }
        __syncthreads();

        #pragma unroll
        for (int k = 0; k < 32; k++) {
            unsigned long long ap[3];
            #pragma unroll
            for (int ri = 0; ri < 3; ri++)
                ap[ri] = *(const unsigned long long*)&xs[k][r0 + 2 * ri];
            #pragma unroll
            for (int j = 0; j < 8; j++) {
                unsigned long long wv =
                    *(const unsigned long long*)&ws2[k][2 * (cg + 16 * j)];
                #pragma unroll
                for (int ri = 0; ri < 3; ri++)
                    asm("fma.rn.f32x2 %0, %1, %2, %0;"
                        : "+l"(acc[ri][j]) : "l"(ap[ri]), "l"(wv));
            }
        }
        __syncthreads();
    }

    #pragma unroll
    for (int ri = 0; ri < 3; ri++) {
        int r = rowBase + r0 + 2 * ri;
        #pragma unroll
        for (int j = 0; j < 8; j++) {
            int c = cg + 16 * j;
            float lo, hi;
            asm("mov.b64 {%0, %1}, %2;" : "=f"(lo), "=f"(hi) : "l"(acc[ri][j]));
            if (r < n)     out[(size_t)r * CF + c] = lo;
            if (r + 1 < n) out[(size_t)(r + 1) * CF + c] = hi;
        }
    }
}

// ---------------------------------------------------------------------------
// launch
// ---------------------------------------------------------------------------
extern "C" void kernel_launch(void* const* d_in, const int* in_sizes, int n_in,
                              void* d_out, int out_size) {
    const float* x       = (const float*)d_in[0];
    const int*   pool_ei = (const int*)d_in[1];     // [2, E_pool] int32
    const float* pool_w  = (const float*)d_in[2];
    const int*   ei      = (const int*)d_in[3];     // [2, E] int32
    const float* ew      = (const float*)d_in[4];
    const float* W1r     = (const float*)d_in[5];
    const float* W1n     = (const float*)d_in[6];
    const float* b1      = (const float*)d_in[7];
    const float* W2r     = (const float*)d_in[8];
    const float* W2n     = (const float*)d_in[9];
    const float* b2      = (const float*)d_in[10];

    int Ep = in_sizes[2];   // pooling edge count
    int E  = in_sizes[4];   // coarse edge count

    float *pooled, *S, *h1;
    int *deg_c, *off_c, *cur_c, *csrc_c;
    int *deg_p, *off_p, *cur_p, *csrc_p;
    float *cw_c, *cw_p;
    cudaGetSymbolAddress((void**)&pooled, g_pooled);
    cudaGetSymbolAddress((void**)&S,      g_S);
    cudaGetSymbolAddress((void**)&h1,     g_h1);
    cudaGetSymbolAddress((void**)&deg_c,  g_deg_c);
    cudaGetSymbolAddress((void**)&off_c,  g_off_c);
    cudaGetSymbolAddress((void**)&cur_c,  g_cur_c);
    cudaGetSymbolAddress((void**)&csrc_c, g_csrc_c);
    cudaGetSymbolAddress((void**)&cw_c,   g_cw_c);
    cudaGetSymbolAddress((void**)&deg_p,  g_deg_p);
    cudaGetSymbolAddress((void**)&off_p,  g_off_p);
    cudaGetSymbolAddress((void**)&cur_p,  g_cur_p);
    cudaGetSymbolAddress((void**)&csrc_p, g_csrc_p);
    cudaGetSymbolAddress((void**)&cw_p,   g_cw_p);

    // 1. CSR build (coarse CSR reused by both conv layers)
    zero_deg_kernel<<<(NC + 255) / 256, 256>>>(deg_c, deg_p, NC);
    {
        int tot = E + Ep;
        hist2_kernel<<<(tot + 255) / 256, 256>>>(ei + E, deg_c, E, pool_ei + Ep, deg_p, Ep);
    }
    scan2_kernel<<<2, 1024>>>(deg_c, off_c, cur_c, deg_p, off_p, cur_p, NC);
    {
        int tot = E + Ep;
        fill2_kernel<<<(tot + 255) / 256, 256>>>(ei, ei + E, ew, cur_c, csrc_c, cw_c, E,
                                                 pool_ei, pool_ei + Ep, pool_w, cur_p, csrc_p, cw_p, Ep);
    }

    const int gwarps = (NC * 32 + 255) / 256;

    // 2. pooled = gather(w * x[src]) fine -> coarse
    gather_kernel<<<gwarps, 256>>>(x, off_p, deg_p, csrc_p, cw_p, pooled, NC);

    // 3. S = gather(w * pooled[src])
    gather_kernel<<<gwarps, 256>>>(pooled, off_c, deg_c, csrc_c, cw_c, S, NC);

    // 4. h1 = pooled @ W1r + S @ W1n + b1
    gemm_kernel<<<(NC + TR - 1) / TR, 256>>>(pooled, S, W1r, W1n, b1, h1, NC);

    // 5. S = gather(w * h1[src])
    gather_kernel<<<gwarps, 256>>>(h1, off_c, deg_c, csrc_c, cw_c, S, NC);

    // 6. out = h1 @ W2r + S @ W2n + b2
    gemm_kernel<<<(NC + TR - 1) / TR, 256>>>(h1, S, W2r, W2n, b2, (float*)d_out, NC);
}

// round 5
// speedup vs baseline: 1.3568x; 1.2971x over previous
#include <cuda_runtime.h>
#include <cuda_bf16.h>
#include <cstdint>

#define NC 25000
#define CF 128
#define EMAX 400000
#define EPMAX 200000

// ---------------- scratch (__device__ globals; no allocs allowed) ----------
__device__ float g_pooled[NC * CF];
__device__ float g_S[NC * CF];
__device__ float g_h1[NC * CF];

__device__ int   g_deg_c[NC];
__device__ int   g_off_c[NC];
__device__ int   g_cur_c[NC];
__device__ int2  g_ed_c[EMAX];

__device__ int   g_deg_p[NC];
__device__ int   g_off_p[NC];
__device__ int   g_cur_p[NC];
__device__ int2  g_ed_p[EPMAX];

// ---------------- CSR build -------------------------------------------------
__global__ void zero_deg_kernel(int* __restrict__ a, int* __restrict__ b, int n) {
    int i = blockIdx.x * blockDim.x + threadIdx.x;
    if (i < n) { a[i] = 0; b[i] = 0; }
}

__global__ void hist2_kernel(const int* __restrict__ dstC, int* __restrict__ degC, int EC,
                             const int* __restrict__ dstP, int* __restrict__ degP, int EP_) {
    int i = blockIdx.x * blockDim.x + threadIdx.x;
    if (i < EC) {
        atomicAdd(&degC[__ldg(&dstC[i])], 1);
    } else {
        int k = i - EC;
        if (k < EP_) atomicAdd(&degP[__ldg(&dstP[k])], 1);
    }
}

__global__ void scan2_kernel(const int* __restrict__ degA, int* __restrict__ offA, int* __restrict__ curA,
                             const int* __restrict__ degB, int* __restrict__ offB, int* __restrict__ curB,
                             int n) {
    const int* deg = blockIdx.x ? degB : degA;
    int* off = blockIdx.x ? offB : offA;
    int* cur = blockIdx.x ? curB : curA;

    __shared__ int ssum[1024];
    int tid = threadIdx.x;
    const int CH = (n + 1023) / 1024;
    int base = tid * CH;
    int s = 0;
    for (int i = 0; i < CH; i++) {
        int idx = base + i;
        if (idx < n) s += deg[idx];
    }
    ssum[tid] = s;
    __syncthreads();
    for (int d = 1; d < 1024; d <<= 1) {
        int v = (tid >= d) ? ssum[tid - d] : 0;
        __syncthreads();
        ssum[tid] += v;
        __syncthreads();
    }
    int run = (tid == 0) ? 0 : ssum[tid - 1];
    for (int i = 0; i < CH; i++) {
        int idx = base + i;
        if (idx < n) {
            off[idx] = run;
            cur[idx] = run;
            run += deg[idx];
        }
    }
}

__global__ void fill2_kernel(const int* __restrict__ srcC, const int* __restrict__ dstC,
                             const float* __restrict__ wC, int* __restrict__ curC,
                             int2* __restrict__ edC, int EC,
                             const int* __restrict__ srcP, const int* __restrict__ dstP,
                             const float* __restrict__ wP, int* __restrict__ curP,
                             int2* __restrict__ edP, int EP_) {
    int i = blockIdx.x * blockDim.x + threadIdx.x;
    if (i < EC) {
        int d = __ldg(&dstC[i]);
        int idx = atomicAdd(&curC[d], 1);
        edC[idx] = make_int2(__ldg(&srcC[i]), __float_as_int(__ldg(&wC[i])));
    } else {
        int k = i - EC;
        if (k < EP_) {
            int d = __ldg(&dstP[k]);
            int idx = atomicAdd(&curP[d], 1);
            edP[idx] = make_int2(__ldg(&srcP[k]), __float_as_int(__ldg(&wP[k])));
        }
    }
}

// ---------------- gather: out[node] = sum_j w_j * X[src_j] (warp/node) ------
__global__ void gather_kernel(const float* __restrict__ X,
                              const int* __restrict__ off,
                              const int* __restrict__ deg,
                              const int2* __restrict__ ed,
                              float* __restrict__ out, int n) {
    int node = (int)((blockIdx.x * blockDim.x + threadIdx.x) >> 5);
    int lane = threadIdx.x & 31;
    if (node >= n) return;
    int o = __ldg(&off[node]);
    int d = __ldg(&deg[node]);
    float4 acc = make_float4(0.f, 0.f, 0.f, 0.f);
    int j = 0;
    for (; j + 8 <= d; j += 8) {
        int2 e[8];
        #pragma unroll
        for (int u = 0; u < 8; u++) e[u] = __ldg(&ed[o + j + u]);
        float4 v[8];
        #pragma unroll
        for (int u = 0; u < 8; u++)
            v[u] = *(const float4*)(X + (size_t)e[u].x * CF + lane * 4);
        #pragma unroll
        for (int u = 0; u < 8; u++) {
            float w = __int_as_float(e[u].y);
            acc.x = fmaf(w, v[u].x, acc.x);
            acc.y = fmaf(w, v[u].y, acc.y);
            acc.z = fmaf(w, v[u].z, acc.z);
            acc.w = fmaf(w, v[u].w, acc.w);
        }
    }
    for (; j < d; j++) {
        int2 e = __ldg(&ed[o + j]);
        float w = __int_as_float(e.y);
        float4 v = *(const float4*)(X + (size_t)e.x * CF + lane * 4);
        acc.x = fmaf(w, v.x, acc.x);
        acc.y = fmaf(w, v.y, acc.y);
        acc.z = fmaf(w, v.z, acc.z);
        acc.w = fmaf(w, v.w, acc.w);
    }
    *(float4*)(out + (size_t)node * CF + lane * 4) = acc;
}

// ---------------- mma.sync bf16 3x-split GEMM -------------------------------
// out = A @ Wr + B @ Wn + bias   (A,B: [n,128] f32; W: [128,128] f32 k-major)
// Equivalent C = X[n,256] @ W[256,128], K processed in 4 chunks of 64.
// Split f32 -> bf16 hi + lo at staging; accumulate hi*hi + hi*lo + lo*hi.
// Block: 64 rows x 128 cols, 256 threads (8 warps, warp tile 32x32).
// Fragments: A via ldmatrix.x4 (xor-swizzled smem), B via ldmatrix.x4.trans.
#define XS_HI 0
#define XS_LO 8192
#define WS_HI 16384
#define WS_LO 32768
#define GEMM_SMEM 49152

__device__ __forceinline__ uint32_t smem_u32(const void* p) {
    uint32_t a;
    asm("{ .reg .u64 t; cvta.to.shared.u64 t, %1; cvt.u32.u64 %0, t; }" : "=r"(a) : "l"(p));
    return a;
}
__device__ __forceinline__ void ldsm_x4(uint32_t* r, uint32_t addr) {
    asm volatile("ldmatrix.sync.aligned.m8n8.x4.shared.b16 {%0,%1,%2,%3}, [%4];"
                 : "=r"(r[0]), "=r"(r[1]), "=r"(r[2]), "=r"(r[3]) : "r"(addr));
}
__device__ __forceinline__ void ldsm_x4_t(uint32_t* r, uint32_t addr) {
    asm volatile("ldmatrix.sync.aligned.m8n8.x4.trans.shared.b16 {%0,%1,%2,%3}, [%4];"
                 : "=r"(r[0]), "=r"(r[1]), "=r"(r[2]), "=r"(r[3]) : "r"(addr));
}
__device__ __forceinline__ void mma_bf16(float* c, const uint32_t* a, const uint32_t* b) {
    asm volatile("mma.sync.aligned.m16n8k16.row.col.f32.bf16.bf16.f32 "
                 "{%0,%1,%2,%3}, {%4,%5,%6,%7}, {%8,%9}, {%0,%1,%2,%3};"
                 : "+f"(c[0]), "+f"(c[1]), "+f"(c[2]), "+f"(c[3])
                 : "r"(a[0]), "r"(a[1]), "r"(a[2]), "r"(a[3]), "r"(b[0]), "r"(b[1]));
}
__device__ __forceinline__ void split_pack(const float* v, uint32_t& hi, uint32_t& lo) {
    __nv_bfloat16 h0 = __float2bfloat16_rn(v[0]);
    __nv_bfloat16 h1 = __float2bfloat16_rn(v[1]);
    __nv_bfloat16 l0 = __float2bfloat16_rn(v[0] - __bfloat162float(h0));
    __nv_bfloat16 l1 = __float2bfloat16_rn(v[1] - __bfloat162float(h1));
    hi = (uint32_t)__bfloat16_as_ushort(h0) | ((uint32_t)__bfloat16_as_ushort(h1) << 16);
    lo = (uint32_t)__bfloat16_as_ushort(l0) | ((uint32_t)__bfloat16_as_ushort(l1) << 16);
}

__global__ __launch_bounds__(256) void gemm_mma_kernel(
        const float* __restrict__ Afeat,
        const float* __restrict__ Bfeat,
        const float* __restrict__ Wr,
        const float* __restrict__ Wn,
        const float* __restrict__ bias,
        float* __restrict__ out, int n) {
    extern __shared__ char smem[];
    uint32_t sbase = smem_u32(smem);

    int tid  = threadIdx.x;
    int wid  = tid >> 5;
    int lane = tid & 31;
    int gid  = lane >> 2;        // 0..7
    int tig  = lane & 3;         // 0..3
    int wm   = wid & 1;          // 32-row half
    int wn   = wid >> 1;         // 0..3: 32-col quarter
    int rowBase = blockIdx.x * 64;

    // accumulators, init with bias
    float c[2][4][4];
    #pragma unroll
    for (int j = 0; j < 4; j++) {
        int col = wn * 32 + j * 8 + tig * 2;
        float b0 = __ldg(&bias[col]), b1 = __ldg(&bias[col + 1]);
        #pragma unroll
        for (int f = 0; f < 2; f++) {
            c[f][j][0] = b0; c[f][j][1] = b1;
            c[f][j][2] = b0; c[f][j][3] = b1;
        }
    }

    // per-lane ldmatrix address components
    int mat  = lane >> 3;        // 0..3
    int r    = lane & 7;
    int amat_half = mat >> 1;    // k 8-block within 16
    int arl  = wm * 32 + (mat & 1) * 8 + r;          // A row local (frag 0)
    // B: jp pair base offsets (jp = 0, 2), kstep 0
    uint32_t boff[2];
    #pragma unroll
    for (int p = 0; p < 2; p++) {
        int jj  = wn * 4 + p * 2 + (mat >> 1);
        int krl = (mat & 1) * 8 + r;
        boff[p] = (uint32_t)(krl * 256 + ((jj ^ (r << 1)) << 4));
    }

    for (int chunk = 0; chunk < 4; chunk++) {
        const float* X = (chunk < 2) ? Afeat : Bfeat;
        const float* W = (chunk < 2) ? Wr : Wn;
        int colbase  = (chunk & 1) * 64;   // X col offset
        int krowbase = (chunk & 1) * 64;   // W row offset

        // ---- stage X chunk: 64 rows x 64 f32 -> bf16 hi/lo, swizzled ----
        #pragma unroll
        for (int it = 0; it < 2; it++) {
            int u   = it * 256 + tid;      // 0..511
            int row = u >> 3;
            int seg = u & 7;
            int grow = rowBase + row;
            float v[8];
            if (grow < n) {
                float4 a0 = *(const float4*)(X + (size_t)grow * CF + colbase + seg * 8);
                float4 a1 = *(const float4*)(X + (size_t)grow * CF + colbase + seg * 8 + 4);
                v[0]=a0.x; v[1]=a0.y; v[2]=a0.z; v[3]=a0.w;
                v[4]=a1.x; v[5]=a1.y; v[6]=a1.z; v[7]=a1.w;
            } else {
                #pragma unroll
                for (int q = 0; q < 8; q++) v[q] = 0.f;
            }
            uint32_t hi[4], lo[4];
            #pragma unroll
            for (int q = 0; q < 4; q++) split_pack(v + q * 2, hi[q], lo[q]);
            uint32_t off = (uint32_t)(row * 128 + ((seg ^ (row & 7)) << 4));
            *(uint4*)(smem + XS_HI + off) = make_uint4(hi[0], hi[1], hi[2], hi[3]);
            *(uint4*)(smem + XS_LO + off) = make_uint4(lo[0], lo[1], lo[2], lo[3]);
        }
        // ---- stage W chunk: 64 k-rows x 128 n -> bf16 hi/lo, swizzled ----
        #pragma unroll
        for (int it = 0; it < 4; it++) {
            int u    = it * 256 + tid;     // 0..1023
            int krow = u >> 4;
            int seg  = u & 15;
            float v[8];
            float4 a0 = *(const float4*)(W + (size_t)(krowbase + krow) * CF + seg * 8);
            float4 a1 = *(const float4*)(W + (size_t)(krowbase + krow) * CF + seg * 8 + 4);
            v[0]=a0.x; v[1]=a0.y; v[2]=a0.z; v[3]=a0.w;
            v[4]=a1.x; v[5]=a1.y; v[6]=a1.z; v[7]=a1.w;
            uint32_t hi[4], lo[4];
            #pragma unroll
            for (int q = 0; q < 4; q++) split_pack(v + q * 2, hi[q], lo[q]);
            uint32_t off = (uint32_t)(krow * 256 + ((seg ^ ((krow & 7) << 1)) << 4));
            *(uint4*)(smem + WS_HI + off) = make_uint4(hi[0], hi[1], hi[2], hi[3]);
            *(uint4*)(smem + WS_LO + off) = make_uint4(lo[0], lo[1], lo[2], lo[3]);
        }
        __syncthreads();

        // ---- mma over 4 k16-steps ----
        #pragma unroll
        for (int ks = 0; ks < 4; ks++) {
            // A fragments (hi & lo), 2 m-frags
            int segA = ks * 2 + amat_half;
            uint32_t aoff = (uint32_t)(arl * 128 + ((segA ^ r) << 4));
            uint32_t ahi[2][4], alo[2][4];
            ldsm_x4(ahi[0], sbase + XS_HI + aoff);
            ldsm_x4(ahi[1], sbase + XS_HI + aoff + 16 * 128);
            ldsm_x4(alo[0], sbase + XS_LO + aoff);
            ldsm_x4(alo[1], sbase + XS_LO + aoff + 16 * 128);
            #pragma unroll
            for (int p = 0; p < 2; p++) {
                uint32_t bh[4], bl[4];
                uint32_t bo = boff[p] + (uint32_t)(ks * 16 * 256);
                ldsm_x4_t(bh, sbase + WS_HI + bo);
                ldsm_x4_t(bl, sbase + WS_LO + bo);
                #pragma unroll
                for (int jj = 0; jj < 2; jj++) {
                    int j = p * 2 + jj;
                    #pragma unroll
                    for (int f = 0; f < 2; f++) {
                        mma_bf16(c[f][j], ahi[f], bh + jj * 2);
                        mma_bf16(c[f][j], ahi[f], bl + jj * 2);
                        mma_bf16(c[f][j], alo[f], bh + jj * 2);
                    }
                }
            }
        }
        __syncthreads();
    }

    // ---- epilogue ----
    #pragma unroll
    for (int f = 0; f < 2; f++) {
        int row0 = rowBase + wm * 32 + f * 16 + gid;
        #pragma unroll
        for (int j = 0; j < 4; j++) {
            int col = wn * 32 + j * 8 + tig * 2;
            if (row0 < n)
                *(float2*)(out + (size_t)row0 * CF + col) = make_float2(c[f][j][0], c[f][j][1]);
            if (row0 + 8 < n)
                *(float2*)(out + (size_t)(row0 + 8) * CF + col) = make_float2(c[f][j][2], c[f][j][3]);
        }
    }
}

// ---------------- launch ----------------------------------------------------
extern "C" void kernel_launch(void* const* d_in, const int* in_sizes, int n_in,
                              void* d_out, int out_size) {
    const float* x       = (const float*)d_in[0];
    const int*   pool_ei = (const int*)d_in[1];     // [2, E_pool] int32
    const float* pool_w  = (const float*)d_in[2];
    const int*   ei      = (const int*)d_in[3];     // [2, E] int32
    const float* ew      = (const float*)d_in[4];
    const float* W1r     = (const float*)d_in[5];
    const float* W1n     = (const float*)d_in[6];
    const float* b1      = (const float*)d_in[7];
    const float* W2r     = (const float*)d_in[8];
    const float* W2n     = (const float*)d_in[9];
    const float* b2      = (const float*)d_in[10];

    int Ep = in_sizes[2];
    int E  = in_sizes[4];

    float *pooled, *S, *h1;
    int *deg_c, *off_c, *cur_c, *deg_p, *off_p, *cur_p;
    int2 *ed_c, *ed_p;
    cudaGetSymbolAddress((void**)&pooled, g_pooled);
    cudaGetSymbolAddress((void**)&S,      g_S);
    cudaGetSymbolAddress((void**)&h1,     g_h1);
    cudaGetSymbolAddress((void**)&deg_c,  g_deg_c);
    cudaGetSymbolAddress((void**)&off_c,  g_off_c);
    cudaGetSymbolAddress((void**)&cur_c,  g_cur_c);
    cudaGetSymbolAddress((void**)&ed_c,   g_ed_c);
    cudaGetSymbolAddress((void**)&deg_p,  g_deg_p);
    cudaGetSymbolAddress((void**)&off_p,  g_off_p);
    cudaGetSymbolAddress((void**)&cur_p,  g_cur_p);
    cudaGetSymbolAddress((void**)&ed_p,   g_ed_p);

    cudaFuncSetAttribute(gemm_mma_kernel, cudaFuncAttributeMaxDynamicSharedMemorySize, GEMM_SMEM);

    // CSR build (coarse CSR reused by both conv layers)
    zero_deg_kernel<<<(NC + 255) / 256, 256>>>(deg_c, deg_p, NC);
    {
        int tot = E + Ep;
        hist2_kernel<<<(tot + 255) / 256, 256>>>(ei + E, deg_c, E, pool_ei + Ep, deg_p, Ep);
    }
    scan2_kernel<<<2, 1024>>>(deg_c, off_c, cur_c, deg_p, off_p, cur_p, NC);
    {
        int tot = E + Ep;
        fill2_kernel<<<(tot + 255) / 256, 256>>>(ei, ei + E, ew, cur_c, ed_c, E,
                                                 pool_ei, pool_ei + Ep, pool_w, cur_p, ed_p, Ep);
    }

    const int gwarps  = (NC * 32 + 255) / 256;
    const int gblocks = (NC + 63) / 64;

    // pooled = gather(w * x[src])  fine -> coarse
    gather_kernel<<<gwarps, 256>>>(x, off_p, deg_p, ed_p, pooled, NC);

    // S = gather(w * pooled[src])
    gather_kernel<<<gwarps, 256>>>(pooled, off_c, deg_c, ed_c, S, NC);

    // h1 = pooled @ W1r + S @ W1n + b1
    gemm_mma_kernel<<<gblocks, 256, GEMM_SMEM>>>(pooled, S, W1r, W1n, b1, h1, NC);

    // S = gather(w * h1[src])
    gather_kernel<<<gwarps, 256>>>(h1, off_c, deg_c, ed_c, S, NC);

    // out = h1 @ W2r + S @ W2n + b2
    gemm_mma_kernel<<<gblocks, 256, GEMM_SMEM>>>(h1, S, W2r, W2n, b2, (float*)d_out, NC);
}

// round 7
// speedup vs baseline: 1.6722x; 1.2324x over previous
#include <cuda_runtime.h>
#include <cuda_bf16.h>
#include <cstdint>

#define NC 25000
#define CF 128
#define EMAX 400000
#define EPMAX 200000

// ---------------- scratch (__device__ globals; no allocs allowed) ----------
__device__ float g_pooled[NC * CF];
__device__ float g_S[NC * CF];
__device__ float g_h1[NC * CF];

__device__ int   g_deg_c[NC];
__device__ int   g_off_c[NC];
__device__ int   g_rank_c[EMAX];
__device__ int2  g_ed_c[EMAX];

__device__ int   g_deg_p[NC];
__device__ int   g_off_p[NC];
__device__ int   g_rank_p[EPMAX];
__device__ int2  g_ed_p[EPMAX];

// W pre-split: [4 (mat,kchunk) units per layer-pair][hi|lo][4096 u32], swizzled
// unit index = slot*2 + kchunk, slot: 0=W1r,1=W1n,2=W2r,3=W2n
// unit stride = 2*4096 u32; layer stride = 4 units = 32768 u32
__device__ uint32_t g_Wprep[4 * 2 * 2 * 4096];

// ---------------- helpers ---------------------------------------------------
__device__ __forceinline__ uint32_t smem_u32(const void* p) {
    uint32_t a;
    asm("{ .reg .u64 t; cvta.to.shared.u64 t, %1; cvt.u32.u64 %0, t; }" : "=r"(a) : "l"(p));
    return a;
}
__device__ __forceinline__ void ldsm_x4(uint32_t* r, uint32_t addr) {
    asm volatile("ldmatrix.sync.aligned.m8n8.x4.shared.b16 {%0,%1,%2,%3}, [%4];"
                 : "=r"(r[0]), "=r"(r[1]), "=r"(r[2]), "=r"(r[3]) : "r"(addr));
}
__device__ __forceinline__ void ldsm_x4_t(uint32_t* r, uint32_t addr) {
    asm volatile("ldmatrix.sync.aligned.m8n8.x4.trans.shared.b16 {%0,%1,%2,%3}, [%4];"
                 : "=r"(r[0]), "=r"(r[1]), "=r"(r[2]), "=r"(r[3]) : "r"(addr));
}
__device__ __forceinline__ void mma_bf16(float* c, const uint32_t* a, const uint32_t* b) {
    asm volatile("mma.sync.aligned.m16n8k16.row.col.f32.bf16.bf16.f32 "
                 "{%0,%1,%2,%3}, {%4,%5,%6,%7}, {%8,%9}, {%0,%1,%2,%3};"
                 : "+f"(c[0]), "+f"(c[1]), "+f"(c[2]), "+f"(c[3])
                 : "r"(a[0]), "r"(a[1]), "r"(a[2]), "r"(a[3]), "r"(b[0]), "r"(b[1]));
}
__device__ __forceinline__ void split_pack(const float* v, uint32_t& hi, uint32_t& lo) {
    __nv_bfloat16 h0 = __float2bfloat16_rn(v[0]);
    __nv_bfloat16 h1 = __float2bfloat16_rn(v[1]);
    __nv_bfloat16 l0 = __float2bfloat16_rn(v[0] - __bfloat162float(h0));
    __nv_bfloat16 l1 = __float2bfloat16_rn(v[1] - __bfloat162float(h1));
    hi = (uint32_t)__bfloat16_as_ushort(h0) | ((uint32_t)__bfloat16_as_ushort(h1) << 16);
    lo = (uint32_t)__bfloat16_as_ushort(l0) | ((uint32_t)__bfloat16_as_ushort(l1) << 16);
}

// ---------------- W pre-split into swizzled layout ---------------------------
__global__ void prep_w_kernel(const float* __restrict__ W1r, const float* __restrict__ W1n,
                              const float* __restrict__ W2r, const float* __restrict__ W2n,
                              uint32_t* __restrict__ out) {
    int u = blockIdx.x * 256 + threadIdx.x;      // 0..8191 : slot(2b) chunk(1b) krow(6b) seg(4b)
    if (u >= 4 * 2048) return;
    int slot = u >> 11;
    int rem  = u & 2047;
    int chunk = rem >> 10;
    int krow  = (rem >> 4) & 63;
    int seg   = rem & 15;
    const float* W = (slot == 0) ? W1r : (slot == 1) ? W1n : (slot == 2) ? W2r : W2n;
    float4 a0 = *(const float4*)(W + (size_t)(chunk * 64 + krow) * CF + seg * 8);
    float4 a1 = *(const float4*)(W + (size_t)(chunk * 64 + krow) * CF + seg * 8 + 4);
    float v[8] = {a0.x, a0.y, a0.z, a0.w, a1.x, a1.y, a1.z, a1.w};
    uint32_t hi[4], lo[4];
    #pragma unroll
    for (int q = 0; q < 4; q++) split_pack(v + q * 2, hi[q], lo[q]);
    uint32_t off = (uint32_t)(krow * 256 + ((seg ^ ((krow & 7) << 1)) << 4));  // bytes
    uint32_t* base = out + (size_t)(slot * 2 + chunk) * 2 * 4096;
    *(uint4*)((char*)base + off)          = make_uint4(hi[0], hi[1], hi[2], hi[3]);
    *(uint4*)((char*)(base + 4096) + off) = make_uint4(lo[0], lo[1], lo[2], lo[3]);
}

// ---------------- CSR build -------------------------------------------------
__global__ void zero_deg_kernel(int* __restrict__ a, int* __restrict__ b, int n) {
    int i = blockIdx.x * blockDim.x + threadIdx.x;
    if (i < n) { a[i] = 0; b[i] = 0; }
}

// histogram + record within-bin rank (atomicAdd return value)
__global__ void hist2_kernel(const int* __restrict__ dstC, int* __restrict__ degC,
                             int* __restrict__ rankC, int EC,
                             const int* __restrict__ dstP, int* __restrict__ degP,
                             int* __restrict__ rankP, int EP_) {
    int i = blockIdx.x * blockDim.x + threadIdx.x;
    if (i < EC) {
        rankC[i] = atomicAdd(&degC[__ldg(&dstC[i])], 1);
    } else {
        int k = i - EC;
        if (k < EP_) rankP[k] = atomicAdd(&degP[__ldg(&dstP[k])], 1);
    }
}

__global__ void scan2_kernel(const int* __restrict__ degA, int* __restrict__ offA,
                             const int* __restrict__ degB, int* __restrict__ offB,
                             int n) {
    const int* deg = blockIdx.x ? degB : degA;
    int* off = blockIdx.x ? offB : offA;

    __shared__ int ssum[1024];
    int tid = threadIdx.x;
    const int CH = (n + 1023) / 1024;
    int base = tid * CH;
    int s = 0;
    for (int i = 0; i < CH; i++) {
        int idx = base + i;
        if (idx < n) s += deg[idx];
    }
    ssum[tid] = s;
    __syncthreads();
    for (int d = 1; d < 1024; d <<= 1) {
        int v = (tid >= d) ? ssum[tid - d] : 0;
        __syncthreads();
        ssum[tid] += v;
        __syncthreads();
    }
    int run = (tid == 0) ? 0 : ssum[tid - 1];
    for (int i = 0; i < CH; i++) {
        int idx = base + i;
        if (idx < n) {
            off[idx] = run;
            run += deg[idx];
        }
    }
}

// atomic-free fill: slot = off[dst] + rank
__global__ void fill2_kernel(const int* __restrict__ srcC, const int* __restrict__ dstC,
                             const float* __restrict__ wC, const int* __restrict__ offC,
                             const int* __restrict__ rankC, int2* __restrict__ edC, int EC,
                             const int* __restrict__ srcP, const int* __restrict__ dstP,
                             const float* __restrict__ wP, const int* __restrict__ offP,
                             const int* __restrict__ rankP, int2* __restrict__ edP, int EP_) {
    int i = blockIdx.x * blockDim.x + threadIdx.x;
    if (i < EC) {
        int d = __ldg(&dstC[i]);
        int idx = __ldg(&offC[d]) + __ldg(&rankC[i]);
        edC[idx] = make_int2(__ldg(&srcC[i]), __float_as_int(__ldg(&wC[i])));
    } else {
        int k = i - EC;
        if (k < EP_) {
            int d = __ldg(&dstP[k]);
            int idx = __ldg(&offP[d]) + __ldg(&rankP[k]);
            edP[idx] = make_int2(__ldg(&srcP[k]), __float_as_int(__ldg(&wP[k])));
        }
    }
}

// ---------------- gather: out[node] = sum_j w_j * X[src_j] (warp/node) ------
__global__ void gather_kernel(const float* __restrict__ X,
                              const int* __restrict__ off,
                              const int* __restrict__ deg,
                              const int2* __restrict__ ed,
                              float* __restrict__ out, int n) {
    int node = (int)((blockIdx.x * blockDim.x + threadIdx.x) >> 5);
    int lane = threadIdx.x & 31;
    if (node >= n) return;
    int o = __ldg(&off[node]);
    int d = __ldg(&deg[node]);
    float4 acc = make_float4(0.f, 0.f, 0.f, 0.f);
    int j = 0;
    for (; j + 8 <= d; j += 8) {
        int2 e[8];
        #pragma unroll
        for (int u = 0; u < 8; u++) e[u] = __ldg(&ed[o + j + u]);
        float4 v[8];
        #pragma unroll
        for (int u = 0; u < 8; u++)
            v[u] = *(const float4*)(X + (size_t)e[u].x * CF + lane * 4);
        #pragma unroll
        for (int u = 0; u < 8; u++) {
            float w = __int_as_float(e[u].y);
            acc.x = fmaf(w, v[u].x, acc.x);
            acc.y = fmaf(w, v[u].y, acc.y);
            acc.z = fmaf(w, v[u].z, acc.z);
            acc.w = fmaf(w, v[u].w, acc.w);
        }
    }
    for (; j < d; j++) {
        int2 e = __ldg(&ed[o + j]);
        float w = __int_as_float(e.y);
        float4 v = *(const float4*)(X + (size_t)e.x * CF + lane * 4);
        acc.x = fmaf(w, v.x, acc.x);
        acc.y = fmaf(w, v.y, acc.y);
        acc.z = fmaf(w, v.z, acc.z);
        acc.w = fmaf(w, v.w, acc.w);
    }
    *(float4*)(out + (size_t)node * CF + lane * 4) = acc;
}

// ---------------- mma.sync bf16 3x-split GEMM -------------------------------
// out = A @ Wr + B @ Wn + bias; W pre-split (swizzled hi/lo) -> staging = copy.
#define XS_HI 0
#define XS_LO 8192
#define WS_HI 16384
#define WS_LO 32768
#define GEMM_SMEM 49152

__global__ __launch_bounds__(256) void gemm_mma_kernel(
        const float* __restrict__ Afeat,
        const float* __restrict__ Bfeat,
        const uint32_t* __restrict__ Wprep,   // layer base: 4 units x [hi|lo][4096]
        const float* __restrict__ bias,
        float* __restrict__ out, int n) {
    extern __shared__ char smem[];
    uint32_t sbase = smem_u32(smem);

    int tid  = threadIdx.x;
    int wid  = tid >> 5;
    int lane = tid & 31;
    int gid  = lane >> 2;
    int tig  = lane & 3;
    int wm   = wid & 1;
    int wn   = wid >> 1;
    int rowBase = blockIdx.x * 64;

    float c[2][4][4];
    #pragma unroll
    for (int j = 0; j < 4; j++) {
        int col = wn * 32 + j * 8 + tig * 2;
        float b0 = __ldg(&bias[col]), b1 = __ldg(&bias[col + 1]);
        #pragma unroll
        for (int f = 0; f < 2; f++) {
            c[f][j][0] = b0; c[f][j][1] = b1;
            c[f][j][2] = b0; c[f][j][3] = b1;
        }
    }

    int mat  = lane >> 3;
    int r    = lane & 7;
    int amat_half = mat >> 1;
    int arl  = wm * 32 + (mat & 1) * 8 + r;
    uint32_t boff[2];
    #pragma unroll
    for (int p = 0; p < 2; p++) {
        int jj  = wn * 4 + p * 2 + (mat >> 1);
        int krl = (mat & 1) * 8 + r;
        boff[p] = (uint32_t)(krl * 256 + ((jj ^ (r << 1)) << 4));
    }

    for (int chunk = 0; chunk < 4; chunk++) {
        const float* X = (chunk < 2) ? Afeat : Bfeat;
        int colbase = (chunk & 1) * 64;
        const uint32_t* wbase = Wprep + (size_t)chunk * 2 * 4096;  // unit = slot*2 + kchunk

        // ---- stage X chunk: 64 rows x 64 f32 -> bf16 hi/lo, swizzled ----
        #pragma unroll
        for (int it = 0; it < 2; it++) {
            int u   = it * 256 + tid;
            int row = u >> 3;
            int seg = u & 7;
            int grow = rowBase + row;
            float v[8];
            if (grow < n) {
                float4 a0 = *(const float4*)(X + (size_t)grow * CF + colbase + seg * 8);
                float4 a1 = *(const float4*)(X + (size_t)grow * CF + colbase + seg * 8 + 4);
                v[0]=a0.x; v[1]=a0.y; v[2]=a0.z; v[3]=a0.w;
                v[4]=a1.x; v[5]=a1.y; v[6]=a1.z; v[7]=a1.w;
            } else {
                #pragma unroll
                for (int q = 0; q < 8; q++) v[q] = 0.f;
            }
            uint32_t hi[4], lo[4];
            #pragma unroll
            for (int q = 0; q < 4; q++) split_pack(v + q * 2, hi[q], lo[q]);
            uint32_t off = (uint32_t)(row * 128 + ((seg ^ (row & 7)) << 4));
            *(uint4*)(smem + XS_HI + off) = make_uint4(hi[0], hi[1], hi[2], hi[3]);
            *(uint4*)(smem + XS_LO + off) = make_uint4(lo[0], lo[1], lo[2], lo[3]);
        }
        // ---- stage W chunk: pure linear copy of pre-swizzled hi/lo ----
        #pragma unroll
        for (int it = 0; it < 4; it++) {
            int u = it * 256 + tid;       // 0..1023 uint4 slots
            uint4 h = __ldg((const uint4*)wbase + u);
            uint4 l = __ldg((const uint4*)(wbase + 4096) + u);
            *(uint4*)(smem + WS_HI + u * 16) = h;
            *(uint4*)(smem + WS_LO + u * 16) = l;
        }
        __syncthreads();

        // ---- mma over 4 k16-steps ----
        #pragma unroll
        for (int ks = 0; ks < 4; ks++) {
            int segA = ks * 2 + amat_half;
            uint32_t aoff = (uint32_t)(arl * 128 + ((segA ^ r) << 4));
            uint32_t ahi[2][4], alo[2][4];
            ldsm_x4(ahi[0], sbase + XS_HI + aoff);
            ldsm_x4(ahi[1], sbase + XS_HI + aoff + 16 * 128);
            ldsm_x4(alo[0], sbase + XS_LO + aoff);
            ldsm_x4(alo[1], sbase + XS_LO + aoff + 16 * 128);
            #pragma unroll
            for (int p = 0; p < 2; p++) {
                uint32_t bh[4], bl[4];
                uint32_t bo = boff[p] + (uint32_t)(ks * 16 * 256);
                ldsm_x4_t(bh, sbase + WS_HI + bo);
                ldsm_x4_t(bl, sbase + WS_LO + bo);
                #pragma unroll
                for (int jj = 0; jj < 2; jj++) {
                    int j = p * 2 + jj;
                    #pragma unroll
                    for (int f = 0; f < 2; f++) {
                        mma_bf16(c[f][j], ahi[f], bh + jj * 2);
                        mma_bf16(c[f][j], ahi[f], bl + jj * 2);
                        mma_bf16(c[f][j], alo[f], bh + jj * 2);
                    }
                }
            }
        }
        __syncthreads();
    }

    // ---- epilogue ----
    #pragma unroll
    for (int f = 0; f < 2; f++) {
        int row0 = rowBase + wm * 32 + f * 16 + gid;
        #pragma unroll
        for (int j = 0; j < 4; j++) {
            int col = wn * 32 + j * 8 + tig * 2;
            if (row0 < n)
                *(float2*)(out + (size_t)row0 * CF + col) = make_float2(c[f][j][0], c[f][j][1]);
            if (row0 + 8 < n)
                *(float2*)(out + (size_t)(row0 + 8) * CF + col) = make_float2(c[f][j][2], c[f][j][3]);
        }
    }
}

// ---------------- launch ----------------------------------------------------
extern "C" void kernel_launch(void* const* d_in, const int* in_sizes, int n_in,
                              void* d_out, int out_size) {
    const float* x       = (const float*)d_in[0];
    const int*   pool_ei = (const int*)d_in[1];
    const float* pool_w  = (const float*)d_in[2];
    const int*   ei      = (const int*)d_in[3];
    const float* ew      = (const float*)d_in[4];
    const float* W1r     = (const float*)d_in[5];
    const float* W1n     = (const float*)d_in[6];
    const float* b1      = (const float*)d_in[7];
    const float* W2r     = (const float*)d_in[8];
    const float* W2n     = (const float*)d_in[9];
    const float* b2      = (const float*)d_in[10];

    int Ep = in_sizes[2];
    int E  = in_sizes[4];

    float *pooled, *S, *h1;
    int *deg_c, *off_c, *rank_c, *deg_p, *off_p, *rank_p;
    int2 *ed_c, *ed_p;
    uint32_t* wprep;
    cudaGetSymbolAddress((void**)&pooled, g_pooled);
    cudaGetSymbolAddress((void**)&S,      g_S);
    cudaGetSymbolAddress((void**)&h1,     g_h1);
    cudaGetSymbolAddress((void**)&deg_c,  g_deg_c);
    cudaGetSymbolAddress((void**)&off_c,  g_off_c);
    cudaGetSymbolAddress((void**)&rank_c, g_rank_c);
    cudaGetSymbolAddress((void**)&ed_c,   g_ed_c);
    cudaGetSymbolAddress((void**)&deg_p,  g_deg_p);
    cudaGetSymbolAddress((void**)&off_p,  g_off_p);
    cudaGetSymbolAddress((void**)&rank_p, g_rank_p);
    cudaGetSymbolAddress((void**)&ed_p,   g_ed_p);
    cudaGetSymbolAddress((void**)&wprep,  g_Wprep);

    cudaFuncSetAttribute(gemm_mma_kernel, cudaFuncAttributeMaxDynamicSharedMemorySize, GEMM_SMEM);

    // W pre-split (units 0..3 = layer1 W1r/W1n; units 4..7 = layer2 W2r/W2n)
    prep_w_kernel<<<32, 256>>>(W1r, W1n, W2r, W2n, wprep);

    // CSR build (rank-in-histogram; atomic-free fill)
    zero_deg_kernel<<<(NC + 255) / 256, 256>>>(deg_c, deg_p, NC);
    {
        int tot = E + Ep;
        hist2_kernel<<<(tot + 255) / 256, 256>>>(ei + E, deg_c, rank_c, E,
                                                 pool_ei + Ep, deg_p, rank_p, Ep);
    }
    scan2_kernel<<<2, 1024>>>(deg_c, off_c, deg_p, off_p, NC);
    {
        int tot = E + Ep;
        fill2_kernel<<<(tot + 255) / 256, 256>>>(ei, ei + E, ew, off_c, rank_c, ed_c, E,
                                                 pool_ei, pool_ei + Ep, pool_w, off_p, rank_p, ed_p, Ep);
    }

    const int gwarps  = (NC * 32 + 255) / 256;
    const int gblocks = (NC + 63) / 64;

    gather_kernel<<<gwarps, 256>>>(x, off_p, deg_p, ed_p, pooled, NC);
    gather_kernel<<<gwarps, 256>>>(pooled, off_c, deg_c, ed_c, S, NC);
    gemm_mma_kernel<<<gblocks, 256, GEMM_SMEM>>>(pooled, S, wprep, b1, h1, NC);
    gather_kernel<<<gwarps, 256>>>(h1, off_c, deg_c, ed_c, S, NC);
    // layer-2 base: 4 units * (2*4096) u32 = 32768
    gemm_mma_kernel<<<gblocks, 256, GEMM_SMEM>>>(h1, S, wprep + 4 * 2 * 4096, b2, (float*)d_out, NC);
}

// round 8
// speedup vs baseline: 1.7493x; 1.0461x over previous
#include <cuda_runtime.h>
#include <cuda_bf16.h>
#include <cstdint>

#define NC 25000
#define CF 128
#define EMAX 400000
#define EPMAX 200000
#define NTILES 391                 // ceil(NC/64)
#define TILE_U32 8192              // per tile: [c0hi 2048][c0lo 2048][c1hi 2048][c1lo 2048]

// ---------------- scratch (__device__ globals; no allocs allowed) ----------
// node features in split-bf16 tile format (hi/lo planes, GEMM-swizzled)
__device__ uint32_t g_pooled_s[NTILES * TILE_U32];
__device__ uint32_t g_S_s[NTILES * TILE_U32];
__device__ uint32_t g_h1_s[NTILES * TILE_U32];

__device__ int   g_deg_c[NC];
__device__ int   g_off_c[NC];
__device__ int   g_rank_c[EMAX];
__device__ int2  g_ed_c[EMAX];

__device__ int   g_deg_p[NC];
__device__ int   g_off_p[NC];
__device__ int   g_rank_p[EPMAX];
__device__ int2  g_ed_p[EPMAX];

__device__ int   g_cnt[2];         // global bin cursors (coarse, pool)

// W pre-split: 8 units [slot*2+kchunk][hi|lo][4096 u32], swizzled
__device__ uint32_t g_Wprep[4 * 2 * 2 * 4096];

// ---------------- helpers ---------------------------------------------------
__device__ __forceinline__ uint32_t smem_u32(const void* p) {
    uint32_t a;
    asm("{ .reg .u64 t; cvta.to.shared.u64 t, %1; cvt.u32.u64 %0, t; }" : "=r"(a) : "l"(p));
    return a;
}
__device__ __forceinline__ void ldsm_x4(uint32_t* r, uint32_t addr) {
    asm volatile("ldmatrix.sync.aligned.m8n8.x4.shared.b16 {%0,%1,%2,%3}, [%4];"
                 : "=r"(r[0]), "=r"(r[1]), "=r"(r[2]), "=r"(r[3]) : "r"(addr));
}
__device__ __forceinline__ void ldsm_x4_t(uint32_t* r, uint32_t addr) {
    asm volatile("ldmatrix.sync.aligned.m8n8.x4.trans.shared.b16 {%0,%1,%2,%3}, [%4];"
                 : "=r"(r[0]), "=r"(r[1]), "=r"(r[2]), "=r"(r[3]) : "r"(addr));
}
__device__ __forceinline__ void mma_bf16(float* c, const uint32_t* a, const uint32_t* b) {
    asm volatile("mma.sync.aligned.m16n8k16.row.col.f32.bf16.bf16.f32 "
                 "{%0,%1,%2,%3}, {%4,%5,%6,%7}, {%8,%9}, {%0,%1,%2,%3};"
                 : "+f"(c[0]), "+f"(c[1]), "+f"(c[2]), "+f"(c[3])
                 : "r"(a[0]), "r"(a[1]), "r"(a[2]), "r"(a[3]), "r"(b[0]), "r"(b[1]));
}
__device__ __forceinline__ void split_pack(float v0, float v1, uint32_t& hi, uint32_t& lo) {
    __nv_bfloat16 h0 = __float2bfloat16_rn(v0);
    __nv_bfloat16 h1 = __float2bfloat16_rn(v1);
    __nv_bfloat16 l0 = __float2bfloat16_rn(v0 - __bfloat162float(h0));
    __nv_bfloat16 l1 = __float2bfloat16_rn(v1 - __bfloat162float(h1));
    hi = (uint32_t)__bfloat16_as_ushort(h0) | ((uint32_t)__bfloat16_as_ushort(h1) << 16);
    lo = (uint32_t)__bfloat16_as_ushort(l0) | ((uint32_t)__bfloat16_as_ushort(l1) << 16);
}

// ---------------- W pre-split into swizzled layout ---------------------------
__global__ void prep_w_kernel(const float* __restrict__ W1r, const float* __restrict__ W1n,
                              const float* __restrict__ W2r, const float* __restrict__ W2n,
                              uint32_t* __restrict__ out) {
    int u = blockIdx.x * 256 + threadIdx.x;      // slot(2b) chunk(1b) krow(6b) seg(4b)
    if (u >= 4 * 2048) return;
    int slot = u >> 11;
    int rem  = u & 2047;
    int chunk = rem >> 10;
    int krow  = (rem >> 4) & 63;
    int seg   = rem & 15;
    const float* W = (slot == 0) ? W1r : (slot == 1) ? W1n : (slot == 2) ? W2r : W2n;
    float4 a0 = *(const float4*)(W + (size_t)(chunk * 64 + krow) * CF + seg * 8);
    float4 a1 = *(const float4*)(W + (size_t)(chunk * 64 + krow) * CF + seg * 8 + 4);
    float v[8] = {a0.x, a0.y, a0.z, a0.w, a1.x, a1.y, a1.z, a1.w};
    uint32_t hi[4], lo[4];
    #pragma unroll
    for (int q = 0; q < 4; q++) split_pack(v[q * 2], v[q * 2 + 1], hi[q], lo[q]);
    uint32_t off = (uint32_t)(krow * 256 + ((seg ^ ((krow & 7) << 1)) << 4));  // bytes
    uint32_t* base = out + (size_t)(slot * 2 + chunk) * 2 * 4096;
    *(uint4*)((char*)base + off)          = make_uint4(hi[0], hi[1], hi[2], hi[3]);
    *(uint4*)((char*)(base + 4096) + off) = make_uint4(lo[0], lo[1], lo[2], lo[3]);
}

// ---------------- CSR build -------------------------------------------------
__global__ void zero_deg_kernel(int* __restrict__ a, int* __restrict__ b,
                                int* __restrict__ cnt, int n) {
    int i = blockIdx.x * blockDim.x + threadIdx.x;
    if (i < n) { a[i] = 0; b[i] = 0; }
    if (i < 2) cnt[i] = 0;
}

// histogram + record within-bin rank (atomicAdd return value)
__global__ void hist2_kernel(const int* __restrict__ dstC, int* __restrict__ degC,
                             int* __restrict__ rankC, int EC,
                             const int* __restrict__ dstP, int* __restrict__ degP,
                             int* __restrict__ rankP, int EP_) {
    int i = blockIdx.x * blockDim.x + threadIdx.x;
    if (i < EC) {
        rankC[i] = atomicAdd(&degC[__ldg(&dstC[i])], 1);
    } else {
        int k = i - EC;
        if (k < EP_) rankP[k] = atomicAdd(&degP[__ldg(&dstP[k])], 1);
    }
}

// bin offset assignment: block scan + one global atomic per block (order-free)
__global__ void offsets_kernel(const int* __restrict__ degC, int* __restrict__ offC,
                               const int* __restrict__ degP, int* __restrict__ offP,
                               int* __restrict__ cnt, int n) {
    int sel = blockIdx.y;
    const int* deg = sel ? degP : degC;
    int* off = sel ? offP : offC;
    int i = blockIdx.x * 256 + threadIdx.x;
    int lane = threadIdx.x & 31;
    int wid  = threadIdx.x >> 5;

    int d = (i < n) ? deg[i] : 0;
    int incl = d;
    #pragma unroll
    for (int s = 1; s < 32; s <<= 1) {
        int v = __shfl_up_sync(0xFFFFFFFFu, incl, s);
        if (lane >= s) incl += v;
    }
    __shared__ int wsum[8];
    __shared__ int wbase[8];
    __shared__ int blockBase;
    if (lane == 31) wsum[wid] = incl;
    __syncthreads();
    if (wid == 0) {
        int v = (lane < 8) ? wsum[lane] : 0;
        int iv = v;
        #pragma unroll
        for (int s = 1; s < 8; s <<= 1) {
            int t = __shfl_up_sync(0xFFFFFFFFu, iv, s);
            if (lane >= s) iv += t;
        }
        if (lane < 8) wbase[lane] = iv - v;
        if (lane == 7) blockBase = atomicAdd(&cnt[sel], iv);
    }
    __syncthreads();
    if (i < n) off[i] = blockBase + wbase[wid] + (incl - d);
}

// atomic-free fill: slot = off[dst] + rank
__global__ void fill2_kernel(const int* __restrict__ srcC, const int* __restrict__ dstC,
                             const float* __restrict__ wC, const int* __restrict__ offC,
                             const int* __restrict__ rankC, int2* __restrict__ edC, int EC,
                             const int* __restrict__ srcP, const int* __restrict__ dstP,
                             const float* __restrict__ wP, const int* __restrict__ offP,
                             const int* __restrict__ rankP, int2* __restrict__ edP, int EP_) {
    int i = blockIdx.x * blockDim.x + threadIdx.x;
    if (i < EC) {
        int d = __ldg(&dstC[i]);
        int idx = __ldg(&offC[d]) + __ldg(&rankC[i]);
        edC[idx] = make_int2(__ldg(&srcC[i]), __float_as_int(__ldg(&wC[i])));
    } else {
        int k = i - EC;
        if (k < EP_) {
            int d = __ldg(&dstP[k]);
            int idx = __ldg(&offP[d]) + __ldg(&rankP[k]);
            edP[idx] = make_int2(__ldg(&srcP[k]), __float_as_int(__ldg(&wP[k])));
        }
    }
}

// split-tile addressing: lane covers cols [4*lane, 4*lane+4)
// u32 idx within tile = chunk*4096 + row*32 + ((segc ^ (row&7))<<2) + (lane&1)*2
// (hi plane; +2048 for lo). chunk = lane>>4, segc = (lane&15)>>1.
__device__ __forceinline__ void split_write_node(uint32_t* __restrict__ out, int node,
                                                 int lane, float4 acc) {
    int tile = node >> 6, row = node & 63;
    int chunk = lane >> 4, segc = (lane & 15) >> 1;
    uint32_t idx = (uint32_t)tile * TILE_U32 + chunk * 4096 + row * 32 +
                   ((segc ^ (row & 7)) << 2) + (lane & 1) * 2;
    uint32_t h0, l0, h1, l1;
    split_pack(acc.x, acc.y, h0, l0);
    split_pack(acc.z, acc.w, h1, l1);
    *(uint2*)&out[idx]        = make_uint2(h0, h1);
    *(uint2*)&out[idx + 2048] = make_uint2(l0, l1);
}

// ---------------- pooling gather: fp32 in, split out ------------------------
__global__ void gather_pool_kernel(const float* __restrict__ X,
                                   const int* __restrict__ off,
                                   const int* __restrict__ deg,
                                   const int2* __restrict__ ed,
                                   uint32_t* __restrict__ out, int n) {
    int node = (int)((blockIdx.x * blockDim.x + threadIdx.x) >> 5);
    int lane = threadIdx.x & 31;
    if (node >= n) return;
    int o = __ldg(&off[node]);
    int d = __ldg(&deg[node]);
    float4 acc = make_float4(0.f, 0.f, 0.f, 0.f);
    int j = 0;
    for (; j + 8 <= d; j += 8) {
        int2 e[8];
        #pragma unroll
        for (int u = 0; u < 8; u++) e[u] = __ldg(&ed[o + j + u]);
        float4 v[8];
        #pragma unroll
        for (int u = 0; u < 8; u++)
            v[u] = *(const float4*)(X + (size_t)e[u].x * CF + lane * 4);
        #pragma unroll
        for (int u = 0; u < 8; u++) {
            float w = __int_as_float(e[u].y);
            acc.x = fmaf(w, v[u].x, acc.x);
            acc.y = fmaf(w, v[u].y, acc.y);
            acc.z = fmaf(w, v[u].z, acc.z);
            acc.w = fmaf(w, v[u].w, acc.w);
        }
    }
    for (; j < d; j++) {
        int2 e = __ldg(&ed[o + j]);
        float w = __int_as_float(e.y);
        float4 v = *(const float4*)(X + (size_t)e.x * CF + lane * 4);
        acc.x = fmaf(w, v.x, acc.x);
        acc.y = fmaf(w, v.y, acc.y);
        acc.z = fmaf(w, v.z, acc.z);
        acc.w = fmaf(w, v.w, acc.w);
    }
    split_write_node(out, node, lane, acc);
}

// ---------------- coarse gather: split in, split out ------------------------
__global__ void gather_split_kernel(const uint32_t* __restrict__ X,
                                    const int* __restrict__ off,
                                    const int* __restrict__ deg,
                                    const int2* __restrict__ ed,
                                    uint32_t* __restrict__ out, int n) {
    int node = (int)((blockIdx.x * blockDim.x + threadIdx.x) >> 5);
    int lane = threadIdx.x & 31;
    if (node >= n) return;
    int o = __ldg(&off[node]);
    int d = __ldg(&deg[node]);
    int laneBase = (lane >> 4) * 4096 + (lane & 1) * 2;
    int segc = (lane & 15) >> 1;
    float4 acc = make_float4(0.f, 0.f, 0.f, 0.f);
    int j = 0;
    for (; j + 4 <= d; j += 4) {
        int2 e[4];
        #pragma unroll
        for (int u = 0; u < 4; u++) e[u] = __ldg(&ed[o + j + u]);
        uint2 h[4], l[4];
        #pragma unroll
        for (int u = 0; u < 4; u++) {
            int s = e[u].x;
            int row = s & 63;
            uint32_t idx = (uint32_t)(s >> 6) * TILE_U32 + row * 32 +
                           ((segc ^ (row & 7)) << 2) + laneBase;
            h[u] = *(const uint2*)&X[idx];
            l[u] = *(const uint2*)&X[idx + 2048];
        }
        #pragma unroll
        for (int u = 0; u < 4; u++) {
            float w = __int_as_float(e[u].y);
            float f0 = __uint_as_float(h[u].x << 16)          + __uint_as_float(l[u].x << 16);
            float f1 = __uint_as_float(h[u].x & 0xFFFF0000u)  + __uint_as_float(l[u].x & 0xFFFF0000u);
            float f2 = __uint_as_float(h[u].y << 16)          + __uint_as_float(l[u].y << 16);
            float f3 = __uint_as_float(h[u].y & 0xFFFF0000u)  + __uint_as_float(l[u].y & 0xFFFF0000u);
            acc.x = fmaf(w, f0, acc.x);
            acc.y = fmaf(w, f1, acc.y);
            acc.z = fmaf(w, f2, acc.z);
            acc.w = fmaf(w, f3, acc.w);
        }
    }
    for (; j < d; j++) {
        int2 e = __ldg(&ed[o + j]);
        int s = e.x;
        int row = s & 63;
        uint32_t idx = (uint32_t)(s >> 6) * TILE_U32 + row * 32 +
                       ((segc ^ (row & 7)) << 2) + laneBase;
        uint2 h = *(const uint2*)&X[idx];
        uint2 l = *(const uint2*)&X[idx + 2048];
        float w = __int_as_float(e.y);
        float f0 = __uint_as_float(h.x << 16)         + __uint_as_float(l.x << 16);
        float f1 = __uint_as_float(h.x & 0xFFFF0000u) + __uint_as_float(l.x & 0xFFFF0000u);
        float f2 = __uint_as_float(h.y << 16)         + __uint_as_float(l.y << 16);
        float f3 = __uint_as_float(h.y & 0xFFFF0000u) + __uint_as_float(l.y & 0xFFFF0000u);
        acc.x = fmaf(w, f0, acc.x);
        acc.y = fmaf(w, f1, acc.y);
        acc.z = fmaf(w, f2, acc.z);
        acc.w = fmaf(w, f3, acc.w);
    }
    split_write_node(out, node, lane, acc);
}

// ---------------- mma.sync bf16 3x-split GEMM (split-format inputs) ---------
// out = A @ Wr + B @ Wn + bias; X and W staging are pure linear copies.
#define XS_HI 0
#define XS_LO 8192
#define WS_HI 16384
#define WS_LO 32768
#define GEMM_SMEM 49152

__global__ __launch_bounds__(256) void gemm_mma_kernel(
        const uint32_t* __restrict__ Asp,
        const uint32_t* __restrict__ Bsp,
        const uint32_t* __restrict__ Wprep,
        const float* __restrict__ bias,
        float* __restrict__ outF,
        uint32_t* __restrict__ outS,
        int split_out, int n) {
    extern __shared__ char smem[];
    uint32_t sbase = smem_u32(smem);

    int tid  = threadIdx.x;
    int wid  = tid >> 5;
    int lane = tid & 31;
    int gid  = lane >> 2;
    int tig  = lane & 3;
    int wm   = wid & 1;
    int wn   = wid >> 1;
    int tile = blockIdx.x;
    int rowBase = tile * 64;

    float c[2][4][4];
    #pragma unroll
    for (int j = 0; j < 4; j++) {
        int col = wn * 32 + j * 8 + tig * 2;
        float b0 = __ldg(&bias[col]), b1 = __ldg(&bias[col + 1]);
        #pragma unroll
        for (int f = 0; f < 2; f++) {
            c[f][j][0] = b0; c[f][j][1] = b1;
            c[f][j][2] = b0; c[f][j][3] = b1;
        }
    }

    int mat  = lane >> 3;
    int r    = lane & 7;
    int amat_half = mat >> 1;
    int arl  = wm * 32 + (mat & 1) * 8 + r;
    uint32_t boff[2];
    #pragma unroll
    for (int p = 0; p < 2; p++) {
        int jj  = wn * 4 + p * 2 + (mat >> 1);
        int krl = (mat & 1) * 8 + r;
        boff[p] = (uint32_t)(krl * 256 + ((jj ^ (r << 1)) << 4));
    }

    for (int chunk = 0; chunk < 4; chunk++) {
        const uint32_t* Xs = (chunk < 2) ? Asp : Bsp;
        const uint32_t* xbase = Xs + (size_t)tile * TILE_U32 + (chunk & 1) * 4096;
        const uint32_t* wbase = Wprep + (size_t)chunk * 2 * 4096;

        // ---- stage X chunk: linear copy of pre-swizzled hi/lo planes ----
        #pragma unroll
        for (int it = 0; it < 2; it++) {
            int u = it * 256 + tid;       // 0..511 uint4
            uint4 h = __ldg((const uint4*)xbase + u);
            uint4 l = __ldg((const uint4*)(xbase + 2048) + u);
            *(uint4*)(smem + XS_HI + u * 16) = h;
            *(uint4*)(smem + XS_LO + u * 16) = l;
        }
        // ---- stage W chunk: linear copy ----
        #pragma unroll
        for (int it = 0; it < 4; it++) {
            int u = it * 256 + tid;       // 0..1023 uint4
            uint4 h = __ldg((const uint4*)wbase + u);
            uint4 l = __ldg((const uint4*)(wbase + 4096) + u);
            *(uint4*)(smem + WS_HI + u * 16) = h;
            *(uint4*)(smem + WS_LO + u * 16) = l;
        }
        __syncthreads();

        // ---- mma over 4 k16-steps ----
        #pragma unroll
        for (int ks = 0; ks < 4; ks++) {
            int segA = ks * 2 + amat_half;
            uint32_t aoff = (uint32_t)(arl * 128 + ((segA ^ r) << 4));
            uint32_t ahi[2][4], alo[2][4];
            ldsm_x4(ahi[0], sbase + XS_HI + aoff);
            ldsm_x4(ahi[1], sbase + XS_HI + aoff + 16 * 128);
            ldsm_x4(alo[0], sbase + XS_LO + aoff);
            ldsm_x4(alo[1], sbase + XS_LO + aoff + 16 * 128);
            #pragma unroll
            for (int p = 0; p < 2; p++) {
                uint32_t bh[4], bl[4];
                uint32_t bo = boff[p] + (uint32_t)(ks * 16 * 256);
                ldsm_x4_t(bh, sbase + WS_HI + bo);
                ldsm_x4_t(bl, sbase + WS_LO + bo);
                #pragma unroll
                for (int jj = 0; jj < 2; jj++) {
                    int j = p * 2 + jj;
                    #pragma unroll
                    for (int f = 0; f < 2; f++) {
                        mma_bf16(c[f][j], ahi[f], bh + jj * 2);
                        mma_bf16(c[f][j], ahi[f], bl + jj * 2);
                        mma_bf16(c[f][j], alo[f], bh + jj * 2);
                    }
                }
            }
        }
        __syncthreads();
    }

    // ---- epilogue ----
    if (split_out) {
        // write split-tile format (whole tile valid to write; tail rows unused)
        #pragma unroll
        for (int f = 0; f < 2; f++) {
            #pragma unroll
            for (int rr = 0; rr < 2; rr++) {
                int lrow = wm * 32 + f * 16 + rr * 8 + gid;
                #pragma unroll
                for (int j = 0; j < 4; j++) {
                    int col = wn * 32 + j * 8 + tig * 2;
                    int chunk = col >> 6;
                    int ccol  = col & 63;
                    int seg   = ccol >> 3;
                    uint32_t idx = (uint32_t)tile * TILE_U32 + chunk * 4096 + lrow * 32 +
                                   ((seg ^ (lrow & 7)) << 2) + (tig >> 1) * 2 + (tig & 1);
                    uint32_t h, l;
                    split_pack(c[f][j][rr * 2], c[f][j][rr * 2 + 1], h, l);
                    outS[idx]        = h;
                    outS[idx + 2048] = l;
                }
            }
        }
    } else {
        #pragma unroll
        for (int f = 0; f < 2; f++) {
            int row0 = rowBase + wm * 32 + f * 16 + gid;
            #pragma unroll
            for (int j = 0; j < 4; j++) {
                int col = wn * 32 + j * 8 + tig * 2;
                if (row0 < n)
                    *(float2*)(outF + (size_t)row0 * CF + col) = make_float2(c[f][j][0], c[f][j][1]);
                if (row0 + 8 < n)
                    *(float2*)(outF + (size_t)(row0 + 8) * CF + col) = make_float2(c[f][j][2], c[f][j][3]);
            }
        }
    }
}

// ---------------- launch ----------------------------------------------------
extern "C" void kernel_launch(void* const* d_in, const int* in_sizes, int n_in,
                              void* d_out, int out_size) {
    const float* x       = (const float*)d_in[0];
    const int*   pool_ei = (const int*)d_in[1];
    const float* pool_w  = (const float*)d_in[2];
    const int*   ei      = (const int*)d_in[3];
    const float* ew      = (const float*)d_in[4];
    const float* W1r     = (const float*)d_in[5];
    const float* W1n     = (const float*)d_in[6];
    const float* b1      = (const float*)d_in[7];
    const float* W2r     = (const float*)d_in[8];
    const float* W2n     = (const float*)d_in[9];
    const float* b2      = (const float*)d_in[10];

    int Ep = in_sizes[2];
    int E  = in_sizes[4];

    uint32_t *pooled_s, *S_s, *h1_s, *wprep;
    int *deg_c, *off_c, *rank_c, *deg_p, *off_p, *rank_p, *cnt;
    int2 *ed_c, *ed_p;
    cudaGetSymbolAddress((void**)&pooled_s, g_pooled_s);
    cudaGetSymbolAddress((void**)&S_s,      g_S_s);
    cudaGetSymbolAddress((void**)&h1_s,     g_h1_s);
    cudaGetSymbolAddress((void**)&deg_c,    g_deg_c);
    cudaGetSymbolAddress((void**)&off_c,    g_off_c);
    cudaGetSymbolAddress((void**)&rank_c,   g_rank_c);
    cudaGetSymbolAddress((void**)&ed_c,     g_ed_c);
    cudaGetSymbolAddress((void**)&deg_p,    g_deg_p);
    cudaGetSymbolAddress((void**)&off_p,    g_off_p);
    cudaGetSymbolAddress((void**)&rank_p,   g_rank_p);
    cudaGetSymbolAddress((void**)&ed_p,     g_ed_p);
    cudaGetSymbolAddress((void**)&cnt,      g_cnt);
    cudaGetSymbolAddress((void**)&wprep,    g_Wprep);

    cudaFuncSetAttribute(gemm_mma_kernel, cudaFuncAttributeMaxDynamicSharedMemorySize, GEMM_SMEM);

    // W pre-split (units 0..3 = layer1; 4..7 = layer2)
    prep_w_kernel<<<32, 256>>>(W1r, W1n, W2r, W2n, wprep);

    // CSR build
    zero_deg_kernel<<<(NC + 255) / 256, 256>>>(deg_c, deg_p, cnt, NC);
    {
        int tot = E + Ep;
        hist2_kernel<<<(tot + 255) / 256, 256>>>(ei + E, deg_c, rank_c, E,
                                                 pool_ei + Ep, deg_p, rank_p, Ep);
    }
    offsets_kernel<<<dim3((NC + 255) / 256, 2), 256>>>(deg_c, off_c, deg_p, off_p, cnt, NC);
    {
        int tot = E + Ep;
        fill2_kernel<<<(tot + 255) / 256, 256>>>(ei, ei + E, ew, off_c, rank_c, ed_c, E,
                                                 pool_ei, pool_ei + Ep, pool_w, off_p, rank_p, ed_p, Ep);
    }

    const int gwarps = (NC * 32 + 255) / 256;

    // pooled = gather(w * x[src])  fine -> coarse (fp32 in, split out)
    gather_pool_kernel<<<gwarps, 256>>>(x, off_p, deg_p, ed_p, pooled_s, NC);

    // S = gather(w * pooled[src])  (split in, split out)
    gather_split_kernel<<<gwarps, 256>>>(pooled_s, off_c, deg_c, ed_c, S_s, NC);

    // h1 = pooled @ W1r + S @ W1n + b1   (split out)
    gemm_mma_kernel<<<NTILES, 256, GEMM_SMEM>>>(pooled_s, S_s, wprep, b1,
                                                nullptr, h1_s, 1, NC);

    // S = gather(w * h1[src])
    gather_split_kernel<<<gwarps, 256>>>(h1_s, off_c, deg_c, ed_c, S_s, NC);

    // out = h1 @ W2r + S @ W2n + b2   (fp32 out)
    gemm_mma_kernel<<<NTILES, 256, GEMM_SMEM>>>(h1_s, S_s, wprep + 4 * 2 * 4096, b2,
                                                (float*)d_out, nullptr, 0, NC);
}